// round 4
// baseline (speedup 1.0000x reference)
#include <cuda_runtime.h>
#include <cstdint>

#define N_NODES 50000
#define N_EDGES 600000
#define N_GRAPHS 64
#define SCAN_CHUNK 1024
#define N_CHUNKS ((N_NODES + SCAN_CHUNK - 1) / SCAN_CHUNK)  // 49

// ---------------- scratch: referenced DIRECTLY in device code ----------------
__device__ int   g_is64;                          // 1 if index inputs are int64
__device__ float g_deg[N_NODES];                  // deg -> dinv (in place)
__device__ int   g_counts[N_NODES];
__device__ int   g_cursor[N_NODES];
__device__ int   g_rowptr[N_NODES + 1];
__device__ int   g_bsums[64];
__device__ int   g_esrc[N_EDGES];
__device__ float g_enorm[N_EDGES];
__device__ __align__(16) float g_bufA[(size_t)N_NODES * 128];  // GEMM output t
__device__ __align__(16) float g_bufB[(size_t)N_NODES * 128];  // aggregation output h
__device__ float g_pooled[N_GRAPHS * 64];

// load element i of an index array that is either int32 or int64
__device__ __forceinline__ int load_idx(const void* p, long long i) {
    if (g_is64) return (int)((const long long*)p)[i];
    return ((const int*)p)[i];
}

// ---------------- dtype detection from edge_index ----------------
// int64 little-endian: odd int32 slots are high words == 0 (values in [0,50000)).
// int32: odd slots are random edge ids in [0,50000) — all-zero prob ~ 0.
__global__ void k_detect(const int* __restrict__ ei32) {
    if (blockIdx.x == 0 && threadIdx.x == 0) {
        int hi = ei32[1] | ei32[3] | ei32[5] | ei32[7] | ei32[9] | ei32[11];
        g_is64 = (hi == 0) ? 1 : 0;
    }
}

// ---------------- init: deg=1 (self loop), counts=0, cursor=0 ----------------
__global__ void k_init() {
    int i = blockIdx.x * blockDim.x + threadIdx.x;
    if (i < N_NODES) { g_deg[i] = 1.0f; g_counts[i] = 0; g_cursor[i] = 0; }
}

// ---------------- histogram over targets + degree count ----------------
__global__ void k_hist(const void* __restrict__ ei) {
    int i = blockIdx.x * blockDim.x + threadIdx.x;
    if (i < N_EDGES) {
        int c = load_idx(ei, (long long)N_EDGES + i);  // col = target
        if ((unsigned)c < N_NODES) {
            atomicAdd(&g_counts[c], 1);
            atomicAdd(&g_deg[c], 1.0f);
        }
    }
}

__global__ void k_rsqrt() {
    int i = blockIdx.x * blockDim.x + threadIdx.x;
    if (i < N_NODES) g_deg[i] = rsqrtf(g_deg[i]);  // deg >= 1 always
}

// ---------------- two-level exclusive scan of counts -> rowptr ----------------
__global__ void k_scan1() {
    __shared__ int s[SCAN_CHUNK];
    int tid = threadIdx.x;
    int i = blockIdx.x * SCAN_CHUNK + tid;
    int v = (i < N_NODES) ? g_counts[i] : 0;
    s[tid] = v;
    __syncthreads();
#pragma unroll
    for (int off = 1; off < SCAN_CHUNK; off <<= 1) {
        int t = (tid >= off) ? s[tid - off] : 0;
        __syncthreads();
        s[tid] += t;
        __syncthreads();
    }
    if (i < N_NODES) g_rowptr[i] = s[tid] - v;  // exclusive within chunk
    if (tid == SCAN_CHUNK - 1) g_bsums[blockIdx.x] = s[tid];
}

__global__ void k_scan2() {
    if (threadIdx.x == 0 && blockIdx.x == 0) {
        int run = 0;
        for (int b = 0; b < N_CHUNKS; b++) { int v = g_bsums[b]; g_bsums[b] = run; run += v; }
        g_rowptr[N_NODES] = run;
    }
}

__global__ void k_scan3() {
    int i = blockIdx.x * blockDim.x + threadIdx.x;
    if (i < N_NODES) g_rowptr[i] += g_bsums[i / SCAN_CHUNK];
}

// ---------------- bucket edges by target ----------------
__global__ void k_bucket(const void* __restrict__ ei) {
    int i = blockIdx.x * blockDim.x + threadIdx.x;
    if (i < N_EDGES) {
        int r = load_idx(ei, i);                       // row = source
        int c = load_idx(ei, (long long)N_EDGES + i);  // col = target
        if ((unsigned)c < N_NODES && (unsigned)r < N_NODES) {
            int pos = g_rowptr[c] + atomicAdd(&g_cursor[c], 1);
            g_esrc[pos] = r;
            g_enorm[pos] = g_deg[r] * g_deg[c];  // g_deg holds dinv by now
        }
    }
}

// ---------------- GEMM: g_bufA[N,BNtot] = A[N,128] @ W[128,BNtot] ----------------
template <int BNtot, bool RELU>
__global__ void k_gemm(const float* __restrict__ Aext, const float* __restrict__ W) {
    const int K = 128;
    const int TN = BNtot / 16;
    const int N = N_NODES;
    const float* A = RELU ? (const float*)g_bufB : Aext;
    __shared__ float As[64][32];
    __shared__ float Ws[32][BNtot];

    int tx = threadIdx.x & 15;
    int ty = threadIdx.x >> 4;
    int row0 = blockIdx.x * 64;

    float acc[4][TN];
#pragma unroll
    for (int i = 0; i < 4; i++)
#pragma unroll
        for (int j = 0; j < TN; j++) acc[i][j] = 0.0f;

    for (int k0 = 0; k0 < K; k0 += 32) {
        for (int idx = threadIdx.x; idx < 64 * 32; idx += 256) {
            int r = idx >> 5, k = idx & 31;
            float v = 0.0f;
            if (row0 + r < N) v = A[(size_t)(row0 + r) * K + k0 + k];
            if (RELU) v = fmaxf(v, 0.0f);
            As[r][k] = v;
        }
        for (int idx = threadIdx.x; idx < 32 * BNtot; idx += 256) {
            int k = idx / BNtot, c = idx % BNtot;
            Ws[k][c] = W[(size_t)(k0 + k) * BNtot + c];
        }
        __syncthreads();

#pragma unroll
        for (int k = 0; k < 32; k++) {
            float a[4], w[TN];
#pragma unroll
            for (int i = 0; i < 4; i++) a[i] = As[ty + 16 * i][k];
#pragma unroll
            for (int j = 0; j < TN; j++) w[j] = Ws[k][tx + 16 * j];
#pragma unroll
            for (int i = 0; i < 4; i++)
#pragma unroll
                for (int j = 0; j < TN; j++) acc[i][j] += a[i] * w[j];
        }
        __syncthreads();
    }

#pragma unroll
    for (int i = 0; i < 4; i++) {
        int r = row0 + ty + 16 * i;
        if (r < N) {
#pragma unroll
            for (int j = 0; j < TN; j++)
                g_bufA[(size_t)r * BNtot + tx + 16 * j] = acc[i][j];
        }
    }
}

// ---------------- CSR gather: bufB[i] = d2*bufA[i] + b + sum_e norm*bufA[src] ----------------
__global__ void k_gather128(const float* __restrict__ b) {
    int node = (blockIdx.x * blockDim.x + threadIdx.x) >> 5;
    int lane = threadIdx.x & 31;
    if (node >= N_NODES) return;
    const float* t = g_bufA;
    float d = g_deg[node];
    float d2 = d * d;
    float4 self = *reinterpret_cast<const float4*>(t + (size_t)node * 128 + lane * 4);
    float4 bv = *reinterpret_cast<const float4*>(b + lane * 4);
    float4 acc;
    acc.x = fmaf(d2, self.x, bv.x);
    acc.y = fmaf(d2, self.y, bv.y);
    acc.z = fmaf(d2, self.z, bv.z);
    acc.w = fmaf(d2, self.w, bv.w);

    int s = g_rowptr[node], e = g_rowptr[node + 1];
    int i = s;
    for (; i + 1 < e; i += 2) {
        int r0 = g_esrc[i], r1 = g_esrc[i + 1];
        float w0 = g_enorm[i], w1 = g_enorm[i + 1];
        float4 v0 = *reinterpret_cast<const float4*>(t + (size_t)r0 * 128 + lane * 4);
        float4 v1 = *reinterpret_cast<const float4*>(t + (size_t)r1 * 128 + lane * 4);
        acc.x = fmaf(w0, v0.x, acc.x); acc.y = fmaf(w0, v0.y, acc.y);
        acc.z = fmaf(w0, v0.z, acc.z); acc.w = fmaf(w0, v0.w, acc.w);
        acc.x = fmaf(w1, v1.x, acc.x); acc.y = fmaf(w1, v1.y, acc.y);
        acc.z = fmaf(w1, v1.z, acc.z); acc.w = fmaf(w1, v1.w, acc.w);
    }
    if (i < e) {
        int r0 = g_esrc[i];
        float w0 = g_enorm[i];
        float4 v0 = *reinterpret_cast<const float4*>(t + (size_t)r0 * 128 + lane * 4);
        acc.x = fmaf(w0, v0.x, acc.x); acc.y = fmaf(w0, v0.y, acc.y);
        acc.z = fmaf(w0, v0.z, acc.z); acc.w = fmaf(w0, v0.w, acc.w);
    }
    *reinterpret_cast<float4*>(g_bufB + (size_t)node * 128 + lane * 4) = acc;
}

__global__ void k_gather64(const float* __restrict__ b) {
    int node = (blockIdx.x * blockDim.x + threadIdx.x) >> 5;
    int lane = threadIdx.x & 31;
    if (node >= N_NODES) return;
    const float* t = g_bufA;
    float d = g_deg[node];
    float d2 = d * d;
    float2 self = *reinterpret_cast<const float2*>(t + (size_t)node * 64 + lane * 2);
    float2 bv = *reinterpret_cast<const float2*>(b + lane * 2);
    float2 acc;
    acc.x = fmaf(d2, self.x, bv.x);
    acc.y = fmaf(d2, self.y, bv.y);

    int s = g_rowptr[node], e = g_rowptr[node + 1];
    int i = s;
    for (; i + 1 < e; i += 2) {
        int r0 = g_esrc[i], r1 = g_esrc[i + 1];
        float w0 = g_enorm[i], w1 = g_enorm[i + 1];
        float2 v0 = *reinterpret_cast<const float2*>(t + (size_t)r0 * 64 + lane * 2);
        float2 v1 = *reinterpret_cast<const float2*>(t + (size_t)r1 * 64 + lane * 2);
        acc.x = fmaf(w0, v0.x, acc.x); acc.y = fmaf(w0, v0.y, acc.y);
        acc.x = fmaf(w1, v1.x, acc.x); acc.y = fmaf(w1, v1.y, acc.y);
    }
    if (i < e) {
        int r0 = g_esrc[i];
        float w0 = g_enorm[i];
        float2 v0 = *reinterpret_cast<const float2*>(t + (size_t)r0 * 64 + lane * 2);
        acc.x = fmaf(w0, v0.x, acc.x); acc.y = fmaf(w0, v0.y, acc.y);
    }
    *reinterpret_cast<float2*>(g_bufB + (size_t)node * 64 + lane * 2) = acc;
}

// ---------------- mean pool (batch sorted; binary search per graph) ----------------
__global__ void k_pool(const void* __restrict__ batch) {
    int g = blockIdx.x;
    const int N = N_NODES;
    int lo = 0, hi = N;
    while (lo < hi) { int mid = (lo + hi) >> 1; if (load_idx(batch, mid) < g) lo = mid + 1; else hi = mid; }
    int start = lo;
    lo = start; hi = N;
    while (lo < hi) { int mid = (lo + hi) >> 1; if (load_idx(batch, mid) < g + 1) lo = mid + 1; else hi = mid; }
    int end = lo;

    int f = threadIdx.x & 63;
    int grp = threadIdx.x >> 6;  // 0..3
    __shared__ float red[4][64];

    float acc = 0.0f;
    for (int i = start + grp; i < end; i += 4)
        acc += fmaxf(g_bufB[(size_t)i * 64 + f], 0.0f);
    red[grp][f] = acc;
    __syncthreads();
    if (grp == 0) {
        float s = red[0][f] + red[1][f] + red[2][f] + red[3][f];
        float cnt = (float)(end - start);
        g_pooled[g * 64 + f] = s / fmaxf(cnt, 1.0f);
    }
}

// ---------------- FC head ----------------
__global__ void k_fc(const float* __restrict__ Wf1, const float* __restrict__ bf1,
                     const float* __restrict__ Wf2, const float* __restrict__ bf2,
                     float* __restrict__ out) {
    __shared__ float P[64 * 64];
    __shared__ float Hd[64 * 32];
    for (int i = threadIdx.x; i < 64 * 64; i += 256) P[i] = g_pooled[i];
    __syncthreads();
    for (int e = threadIdx.x; e < 64 * 32; e += 256) {
        int gi = e >> 5, j = e & 31;
        float s = bf1[j];
#pragma unroll
        for (int k = 0; k < 64; k++) s += P[gi * 64 + k] * Wf1[k * 32 + j];
        Hd[e] = fmaxf(s, 0.0f);
    }
    __syncthreads();
    for (int e = threadIdx.x; e < 64 * 10; e += 256) {
        int gi = e / 10, j = e % 10;
        float s = bf2[j];
#pragma unroll
        for (int k = 0; k < 32; k++) s += Hd[gi * 32 + k] * Wf2[k * 10 + j];
        out[e] = s;
    }
}

// ---------------- launch ----------------
extern "C" void kernel_launch(void* const* d_in, const int* in_sizes, int n_in,
                              void* d_out, int out_size) {
    // resolve inputs by element count (robust to ordering); W1/W2 and b1/b2
    // share sizes — first occurrence is layer 1.
    const float *x = 0, *W1 = 0, *b1 = 0, *W2 = 0, *b2 = 0, *W3 = 0, *b3 = 0;
    const float *Wf1 = 0, *bf1 = 0, *Wf2 = 0, *bf2 = 0;
    const void *ei = 0, *batch = 0;
    for (int i = 0; i < n_in; i++) {
        const void* p = d_in[i];
        switch (in_sizes[i]) {
            case 6400000: x = (const float*)p; break;
            case 1200000: ei = p; break;
            case 50000:   batch = p; break;
            case 16384:   if (!W1) W1 = (const float*)p; else W2 = (const float*)p; break;
            case 128:     if (!b1) b1 = (const float*)p; else b2 = (const float*)p; break;
            case 8192:    W3 = (const float*)p; break;
            case 64:      b3 = (const float*)p; break;
            case 2048:    Wf1 = (const float*)p; break;
            case 32:      bf1 = (const float*)p; break;
            case 320:     Wf2 = (const float*)p; break;
            case 10:      bf2 = (const float*)p; break;
        }
    }

    const int N = N_NODES, E = N_EDGES;

    // ---- CSR build ----
    k_detect<<<1, 32>>>((const int*)ei);
    k_init<<<(N + 255) / 256, 256>>>();
    k_hist<<<(E + 255) / 256, 256>>>(ei);
    k_scan1<<<N_CHUNKS, SCAN_CHUNK>>>();
    k_scan2<<<1, 32>>>();
    k_scan3<<<(N + 255) / 256, 256>>>();
    k_rsqrt<<<(N + 255) / 256, 256>>>();  // g_deg now holds dinv
    k_bucket<<<(E + 255) / 256, 256>>>(ei);

    int gemm_grid = (N + 63) / 64;
    int gath_grid = (N * 32 + 255) / 256;

    // layer 1
    k_gemm<128, false><<<gemm_grid, 256>>>(x, W1);
    k_gather128<<<gath_grid, 256>>>(b1);
    // layer 2 (relu fused into GEMM A-load)
    k_gemm<128, true><<<gemm_grid, 256>>>(nullptr, W2);
    k_gather128<<<gath_grid, 256>>>(b2);
    // layer 3: F_out = 64
    k_gemm<64, true><<<gemm_grid, 256>>>(nullptr, W3);
    k_gather64<<<gath_grid, 256>>>(b3);

    // pool (relu fused) + FC head
    k_pool<<<N_GRAPHS, 256>>>(batch);
    k_fc<<<1, 256>>>(Wf1, bf1, Wf2, bf2, (float*)d_out);
}

// round 6
// speedup vs baseline: 1.2194x; 1.2194x over previous
#include <cuda_runtime.h>
#include <cuda_bf16.h>
#include <cstdint>

#define N_NODES 50000
#define N_PAD   50048   // 391 * 128
#define N_EDGES 600000
#define N_GRAPHS 64
#define SCAN_CHUNK 1024
#define N_CHUNKS ((N_NODES + SCAN_CHUNK - 1) / SCAN_CHUNK)  // 49

// ---------------- scratch: referenced DIRECTLY in device code ----------------
__device__ int   g_is64;
__device__ float g_deg[N_NODES];                  // dinv
__device__ int   g_counts[N_NODES];
__device__ int   g_cursor[N_NODES];
__device__ int   g_rowptr[N_NODES + 1];
__device__ int   g_bsums[64];
__device__ int   g_esrc[N_EDGES];
__device__ float g_enorm[N_EDGES];
__device__ __align__(16) float g_bufA[(size_t)N_NODES * 128];  // GEMM out t
__device__ __align__(16) float g_bufB[(size_t)N_NODES * 128];  // agg out h
__device__ float g_pooled[N_GRAPHS * 64];
// bf16 split operands; padding rows [50000,50048) are never written -> stay zero
__device__ __align__(16) __nv_bfloat16 g_ahi[(size_t)N_PAD * 128];
__device__ __align__(16) __nv_bfloat16 g_alo[(size_t)N_PAD * 128];
__device__ __align__(16) __nv_bfloat16 g_whi[128 * 128];   // W^T [n][k] hi
__device__ __align__(16) __nv_bfloat16 g_wlo[128 * 128];   // W^T [n][k] lo

// ---------------- helpers ----------------
__device__ __forceinline__ uint32_t smem_u32(const void* p) {
    uint32_t a;
    asm("{ .reg .u64 t; cvta.to.shared.u64 t, %1; cvt.u32.u64 %0, t; }" : "=r"(a) : "l"(p));
    return a;
}
__device__ __forceinline__ void ldsm_x4(uint32_t* r, uint32_t addr) {
    asm volatile("ldmatrix.sync.aligned.m8n8.x4.shared.b16 {%0,%1,%2,%3}, [%4];"
                 : "=r"(r[0]), "=r"(r[1]), "=r"(r[2]), "=r"(r[3]) : "r"(addr));
}
__device__ __forceinline__ void mma_bf16(float* d, const uint32_t* a, uint32_t b0, uint32_t b1) {
    asm volatile(
        "mma.sync.aligned.m16n8k16.row.col.f32.bf16.bf16.f32 "
        "{%0,%1,%2,%3}, {%4,%5,%6,%7}, {%8,%9}, {%0,%1,%2,%3};"
        : "+f"(d[0]), "+f"(d[1]), "+f"(d[2]), "+f"(d[3])
        : "r"(a[0]), "r"(a[1]), "r"(a[2]), "r"(a[3]), "r"(b0), "r"(b1));
}
__device__ __forceinline__ int load_idx(const void* p, long long i) {
    if (g_is64) return (int)((const long long*)p)[i];
    return ((const int*)p)[i];
}

// ---------------- dtype detection ----------------
__global__ void k_detect(const int* __restrict__ ei32) {
    if (blockIdx.x == 0 && threadIdx.x == 0) {
        int hi = ei32[1] | ei32[3] | ei32[5] | ei32[7] | ei32[9] | ei32[11];
        g_is64 = (hi == 0) ? 1 : 0;
    }
}

// ---------------- CSR build ----------------
__global__ void k_init() {
    int i = blockIdx.x * blockDim.x + threadIdx.x;
    if (i < N_NODES) { g_counts[i] = 0; g_cursor[i] = 0; }
}
__global__ void k_hist(const void* __restrict__ ei) {
    int i = blockIdx.x * blockDim.x + threadIdx.x;
    if (i < N_EDGES) {
        int c = load_idx(ei, (long long)N_EDGES + i);
        if ((unsigned)c < N_NODES) atomicAdd(&g_counts[c], 1);
    }
}
__global__ void k_rsqrt() {
    int i = blockIdx.x * blockDim.x + threadIdx.x;
    if (i < N_NODES) g_deg[i] = rsqrtf(1.0f + (float)g_counts[i]);  // + self loop
}
__global__ void k_scan1() {
    __shared__ int s[SCAN_CHUNK];
    int tid = threadIdx.x;
    int i = blockIdx.x * SCAN_CHUNK + tid;
    int v = (i < N_NODES) ? g_counts[i] : 0;
    s[tid] = v;
    __syncthreads();
#pragma unroll
    for (int off = 1; off < SCAN_CHUNK; off <<= 1) {
        int t = (tid >= off) ? s[tid - off] : 0;
        __syncthreads();
        s[tid] += t;
        __syncthreads();
    }
    if (i < N_NODES) g_rowptr[i] = s[tid] - v;
    if (tid == SCAN_CHUNK - 1) g_bsums[blockIdx.x] = s[tid];
}
__global__ void k_scan2() {
    if (threadIdx.x == 0 && blockIdx.x == 0) {
        int run = 0;
        for (int b = 0; b < N_CHUNKS; b++) { int v = g_bsums[b]; g_bsums[b] = run; run += v; }
        g_rowptr[N_NODES] = run;
    }
}
__global__ void k_scan3() {
    int i = blockIdx.x * blockDim.x + threadIdx.x;
    if (i < N_NODES) g_rowptr[i] += g_bsums[i / SCAN_CHUNK];
}
__global__ void k_bucket(const void* __restrict__ ei) {
    int i = blockIdx.x * blockDim.x + threadIdx.x;
    if (i < N_EDGES) {
        int r = load_idx(ei, i);
        int c = load_idx(ei, (long long)N_EDGES + i);
        if ((unsigned)c < N_NODES && (unsigned)r < N_NODES) {
            int pos = g_rowptr[c] + atomicAdd(&g_cursor[c], 1);
            g_esrc[pos] = r;
            g_enorm[pos] = g_deg[r] * g_deg[c];
        }
    }
}

// ---------------- fp32 -> bf16 hi/lo splits ----------------
__global__ void k_splitA(const float* __restrict__ srcExt, int relu) {
    int idx = blockIdx.x * blockDim.x + threadIdx.x;
    if (idx >= N_NODES * 32) return;
    const float* src = srcExt ? srcExt : (const float*)g_bufB;
    float4 v = reinterpret_cast<const float4*>(src)[idx];
    if (relu) {
        v.x = fmaxf(v.x, 0.0f); v.y = fmaxf(v.y, 0.0f);
        v.z = fmaxf(v.z, 0.0f); v.w = fmaxf(v.w, 0.0f);
    }
    __nv_bfloat16 h0 = __float2bfloat16_rn(v.x), h1 = __float2bfloat16_rn(v.y);
    __nv_bfloat16 h2 = __float2bfloat16_rn(v.z), h3 = __float2bfloat16_rn(v.w);
    __nv_bfloat16 l0 = __float2bfloat16_rn(v.x - __bfloat162float(h0));
    __nv_bfloat16 l1 = __float2bfloat16_rn(v.y - __bfloat162float(h1));
    __nv_bfloat16 l2 = __float2bfloat16_rn(v.z - __bfloat162float(h2));
    __nv_bfloat16 l3 = __float2bfloat16_rn(v.w - __bfloat162float(h3));
    __nv_bfloat162 hp0(h0, h1), hp1(h2, h3), lp0(l0, l1), lp1(l2, l3);
    uint2 hv, lv;
    hv.x = *(uint32_t*)&hp0; hv.y = *(uint32_t*)&hp1;
    lv.x = *(uint32_t*)&lp0; lv.y = *(uint32_t*)&lp1;
    reinterpret_cast<uint2*>(g_ahi)[idx] = hv;
    reinterpret_cast<uint2*>(g_alo)[idx] = lv;
}

// W split + transpose: g_whi[n*128+k] = bf16(W[k*Ncols+n])
__global__ void k_splitW(const float* __restrict__ W, int Ncols) {
    int idx = blockIdx.x * blockDim.x + threadIdx.x;
    if (idx >= 128 * Ncols) return;
    int k = idx & 127, n = idx >> 7;
    float w = W[(size_t)k * Ncols + n];
    __nv_bfloat16 h = __float2bfloat16_rn(w);
    __nv_bfloat16 l = __float2bfloat16_rn(w - __bfloat162float(h));
    g_whi[idx] = h;
    g_wlo[idx] = l;
}

// ---------------- mma.sync GEMM: g_bufA[128-tile, NC] = (ahi+alo) @ (whi+wlo)^T ----
// 3-pass compensated bf16: hi*hi + hi*lo + lo*hi, fp32 accum.
// smem rows: 256B (128 bf16), chunk swizzle: chunk ^= (row & 7).
template <int NC>
__global__ void __launch_bounds__(256, 1) k_gemm_mma() {
    extern __shared__ __align__(16) char smem[];
    const int A_HI = 0, A_LO = 32768, B_HI = 65536, B_LO = 65536 + NC * 256;
    int tid = threadIdx.x;
    int wid = tid >> 5, lane = tid & 31;
    int row0 = blockIdx.x * 128;
    uint32_t sb = smem_u32(smem);

    // g2s A tiles (rows always valid: grid*128 == N_PAD, padding rows are zero)
    for (int c = tid; c < 128 * 16; c += 256) {
        int m = c >> 4, kc = c & 15;
        size_t gof = ((size_t)(row0 + m)) * 256 + kc * 16;
        uint4 vh = *reinterpret_cast<const uint4*>(reinterpret_cast<const char*>(g_ahi) + gof);
        uint4 vl = *reinterpret_cast<const uint4*>(reinterpret_cast<const char*>(g_alo) + gof);
        int off = m * 256 + ((kc ^ (m & 7)) * 16);
        *reinterpret_cast<uint4*>(smem + A_HI + off) = vh;
        *reinterpret_cast<uint4*>(smem + A_LO + off) = vl;
    }
    // g2s B tiles (W^T, NC rows x 256B)
    for (int c = tid; c < NC * 16; c += 256) {
        int n = c >> 4, kc = c & 15;
        size_t gof = (size_t)n * 256 + kc * 16;
        uint4 vh = *reinterpret_cast<const uint4*>(reinterpret_cast<const char*>(g_whi) + gof);
        uint4 vl = *reinterpret_cast<const uint4*>(reinterpret_cast<const char*>(g_wlo) + gof);
        int off = n * 256 + ((kc ^ (n & 7)) * 16);
        *reinterpret_cast<uint4*>(smem + B_HI + off) = vh;
        *reinterpret_cast<uint4*>(smem + B_LO + off) = vl;
    }
    __syncthreads();

    const int NT = NC / 16;   // 8-col n-tiles per warp
    const int NP = NC / 32;   // x4 B loads per k-step
    int wm = (wid & 3) * 32;
    int wn = (wid >> 2) * (NC / 2);

    float acc[2][NT][4];
#pragma unroll
    for (int mt = 0; mt < 2; mt++)
#pragma unroll
        for (int nt = 0; nt < NT; nt++)
#pragma unroll
            for (int j = 0; j < 4; j++) acc[mt][nt][j] = 0.0f;

    for (int pass = 0; pass < 3; pass++) {
        int aB = (pass == 2) ? A_LO : A_HI;
        int bB = (pass == 1) ? B_LO : B_HI;
#pragma unroll
        for (int ks = 0; ks < 8; ks++) {  // K = 8 * 16
            uint32_t a[2][4];
#pragma unroll
            for (int mt = 0; mt < 2; mt++) {
                int r = wm + mt * 16 + (lane & 15);
                int ch = ks * 2 + (lane >> 4);
                ldsm_x4(a[mt], sb + aB + r * 256 + ((ch ^ (r & 7)) * 16));
            }
            uint32_t b[NP][4];
#pragma unroll
            for (int p = 0; p < NP; p++) {
                int n = wn + p * 16 + (lane & 7) + ((lane >> 4) << 3);
                int ch = ks * 2 + ((lane >> 3) & 1);
                ldsm_x4(b[p], sb + bB + n * 256 + ((ch ^ (n & 7)) * 16));
            }
#pragma unroll
            for (int mt = 0; mt < 2; mt++)
#pragma unroll
                for (int nt = 0; nt < NT; nt++)
                    mma_bf16(acc[mt][nt], a[mt], b[nt >> 1][(nt & 1) * 2], b[nt >> 1][(nt & 1) * 2 + 1]);
        }
    }

    // epilogue: D frag -> g_bufA
    int gid = lane >> 2, tig = lane & 3;
#pragma unroll
    for (int mt = 0; mt < 2; mt++) {
#pragma unroll
        for (int nt = 0; nt < NT; nt++) {
            int col = wn + nt * 8 + tig * 2;
            int m0 = row0 + wm + mt * 16 + gid;
            if (m0 < N_NODES)
                *reinterpret_cast<float2*>(g_bufA + (size_t)m0 * NC + col) =
                    make_float2(acc[mt][nt][0], acc[mt][nt][1]);
            if (m0 + 8 < N_NODES)
                *reinterpret_cast<float2*>(g_bufA + (size_t)(m0 + 8) * NC + col) =
                    make_float2(acc[mt][nt][2], acc[mt][nt][3]);
        }
    }
}

// ---------------- CSR gather ----------------
__global__ void k_gather128(const float* __restrict__ b) {
    int node = (blockIdx.x * blockDim.x + threadIdx.x) >> 5;
    int lane = threadIdx.x & 31;
    if (node >= N_NODES) return;
    const float* t = g_bufA;
    float d = g_deg[node];
    float d2 = d * d;
    float4 self = *reinterpret_cast<const float4*>(t + (size_t)node * 128 + lane * 4);
    float4 bv = *reinterpret_cast<const float4*>(b + lane * 4);
    float4 acc;
    acc.x = fmaf(d2, self.x, bv.x);
    acc.y = fmaf(d2, self.y, bv.y);
    acc.z = fmaf(d2, self.z, bv.z);
    acc.w = fmaf(d2, self.w, bv.w);

    int s = g_rowptr[node], e = g_rowptr[node + 1];
    int i = s;
    for (; i + 1 < e; i += 2) {
        int r0 = g_esrc[i], r1 = g_esrc[i + 1];
        float w0 = g_enorm[i], w1 = g_enorm[i + 1];
        float4 v0 = *reinterpret_cast<const float4*>(t + (size_t)r0 * 128 + lane * 4);
        float4 v1 = *reinterpret_cast<const float4*>(t + (size_t)r1 * 128 + lane * 4);
        acc.x = fmaf(w0, v0.x, acc.x); acc.y = fmaf(w0, v0.y, acc.y);
        acc.z = fmaf(w0, v0.z, acc.z); acc.w = fmaf(w0, v0.w, acc.w);
        acc.x = fmaf(w1, v1.x, acc.x); acc.y = fmaf(w1, v1.y, acc.y);
        acc.z = fmaf(w1, v1.z, acc.z); acc.w = fmaf(w1, v1.w, acc.w);
    }
    if (i < e) {
        int r0 = g_esrc[i];
        float w0 = g_enorm[i];
        float4 v0 = *reinterpret_cast<const float4*>(t + (size_t)r0 * 128 + lane * 4);
        acc.x = fmaf(w0, v0.x, acc.x); acc.y = fmaf(w0, v0.y, acc.y);
        acc.z = fmaf(w0, v0.z, acc.z); acc.w = fmaf(w0, v0.w, acc.w);
    }
    *reinterpret_cast<float4*>(g_bufB + (size_t)node * 128 + lane * 4) = acc;
}

__global__ void k_gather64(const float* __restrict__ b) {
    int node = (blockIdx.x * blockDim.x + threadIdx.x) >> 5;
    int lane = threadIdx.x & 31;
    if (node >= N_NODES) return;
    const float* t = g_bufA;
    float d = g_deg[node];
    float d2 = d * d;
    float2 self = *reinterpret_cast<const float2*>(t + (size_t)node * 64 + lane * 2);
    float2 bv = *reinterpret_cast<const float2*>(b + lane * 2);
    float2 acc;
    acc.x = fmaf(d2, self.x, bv.x);
    acc.y = fmaf(d2, self.y, bv.y);

    int s = g_rowptr[node], e = g_rowptr[node + 1];
    int i = s;
    for (; i + 1 < e; i += 2) {
        int r0 = g_esrc[i], r1 = g_esrc[i + 1];
        float w0 = g_enorm[i], w1 = g_enorm[i + 1];
        float2 v0 = *reinterpret_cast<const float2*>(t + (size_t)r0 * 64 + lane * 2);
        float2 v1 = *reinterpret_cast<const float2*>(t + (size_t)r1 * 64 + lane * 2);
        acc.x = fmaf(w0, v0.x, acc.x); acc.y = fmaf(w0, v0.y, acc.y);
        acc.x = fmaf(w1, v1.x, acc.x); acc.y = fmaf(w1, v1.y, acc.y);
    }
    if (i < e) {
        int r0 = g_esrc[i];
        float w0 = g_enorm[i];
        float2 v0 = *reinterpret_cast<const float2*>(t + (size_t)r0 * 64 + lane * 2);
        acc.x = fmaf(w0, v0.x, acc.x); acc.y = fmaf(w0, v0.y, acc.y);
    }
    *reinterpret_cast<float2*>(g_bufB + (size_t)node * 64 + lane * 2) = acc;
}

// ---------------- mean pool ----------------
__global__ void k_pool(const void* __restrict__ batch) {
    int g = blockIdx.x;
    const int N = N_NODES;
    int lo = 0, hi = N;
    while (lo < hi) { int mid = (lo + hi) >> 1; if (load_idx(batch, mid) < g) lo = mid + 1; else hi = mid; }
    int start = lo;
    lo = start; hi = N;
    while (lo < hi) { int mid = (lo + hi) >> 1; if (load_idx(batch, mid) < g + 1) lo = mid + 1; else hi = mid; }
    int end = lo;

    int f = threadIdx.x & 63;
    int grp = threadIdx.x >> 6;
    __shared__ float red[4][64];

    float acc = 0.0f;
    for (int i = start + grp; i < end; i += 4)
        acc += fmaxf(g_bufB[(size_t)i * 64 + f], 0.0f);
    red[grp][f] = acc;
    __syncthreads();
    if (grp == 0) {
        float s = red[0][f] + red[1][f] + red[2][f] + red[3][f];
        float cnt = (float)(end - start);
        g_pooled[g * 64 + f] = s / fmaxf(cnt, 1.0f);
    }
}

// ---------------- FC head ----------------
__global__ void k_fc(const float* __restrict__ Wf1, const float* __restrict__ bf1,
                     const float* __restrict__ Wf2, const float* __restrict__ bf2,
                     float* __restrict__ out) {
    __shared__ float P[64 * 64];
    __shared__ float Hd[64 * 32];
    for (int i = threadIdx.x; i < 64 * 64; i += 256) P[i] = g_pooled[i];
    __syncthreads();
    for (int e = threadIdx.x; e < 64 * 32; e += 256) {
        int gi = e >> 5, j = e & 31;
        float s = bf1[j];
#pragma unroll
        for (int k = 0; k < 64; k++) s += P[gi * 64 + k] * Wf1[k * 32 + j];
        Hd[e] = fmaxf(s, 0.0f);
    }
    __syncthreads();
    for (int e = threadIdx.x; e < 64 * 10; e += 256) {
        int gi = e / 10, j = e % 10;
        float s = bf2[j];
#pragma unroll
        for (int k = 0; k < 32; k++) s += Hd[gi * 32 + k] * Wf2[k * 10 + j];
        out[e] = s;
    }
}

// ---------------- launch ----------------
extern "C" void kernel_launch(void* const* d_in, const int* in_sizes, int n_in,
                              void* d_out, int out_size) {
    const float *x = 0, *W1 = 0, *b1 = 0, *W2 = 0, *b2 = 0, *W3 = 0, *b3 = 0;
    const float *Wf1 = 0, *bf1 = 0, *Wf2 = 0, *bf2 = 0;
    const void *ei = 0, *batch = 0;
    for (int i = 0; i < n_in; i++) {
        const void* p = d_in[i];
        switch (in_sizes[i]) {
            case 6400000: x = (const float*)p; break;
            case 1200000: ei = p; break;
            case 50000:   batch = p; break;
            case 16384:   if (!W1) W1 = (const float*)p; else W2 = (const float*)p; break;
            case 128:     if (!b1) b1 = (const float*)p; else b2 = (const float*)p; break;
            case 8192:    W3 = (const float*)p; break;
            case 64:      b3 = (const float*)p; break;
            case 2048:    Wf1 = (const float*)p; break;
            case 32:      bf1 = (const float*)p; break;
            case 320:     Wf2 = (const float*)p; break;
            case 10:      bf2 = (const float*)p; break;
        }
    }

    const int N = N_NODES, E = N_EDGES;
    const int SMEM128 = 65536 + 2 * 128 * 256;  // 131072
    const int SMEM64  = 65536 + 2 * 64 * 256;   // 98304
    cudaFuncSetAttribute(k_gemm_mma<128>, cudaFuncAttributeMaxDynamicSharedMemorySize, SMEM128);
    cudaFuncSetAttribute(k_gemm_mma<64>,  cudaFuncAttributeMaxDynamicSharedMemorySize, SMEM64);

    // ---- CSR build ----
    k_detect<<<1, 32>>>((const int*)ei);
    k_init<<<(N + 255) / 256, 256>>>();
    k_hist<<<(E + 255) / 256, 256>>>(ei);
    k_scan1<<<N_CHUNKS, SCAN_CHUNK>>>();
    k_scan2<<<1, 32>>>();
    k_scan3<<<(N + 255) / 256, 256>>>();
    k_rsqrt<<<(N + 255) / 256, 256>>>();
    k_bucket<<<(E + 255) / 256, 256>>>(ei);

    int gath_grid = (N * 32 + 255) / 256;
    int split_grid = (N * 32 + 255) / 256;
    int gemm_grid = N_PAD / 128;  // 391

    // layer 1
    k_splitW<<<(128 * 128 + 255) / 256, 256>>>(W1, 128);
    k_splitA<<<split_grid, 256>>>(x, 0);
    k_gemm_mma<128><<<gemm_grid, 256, SMEM128>>>();
    k_gather128<<<gath_grid, 256>>>(b1);
    // layer 2
    k_splitW<<<(128 * 128 + 255) / 256, 256>>>(W2, 128);
    k_splitA<<<split_grid, 256>>>(nullptr, 1);
    k_gemm_mma<128><<<gemm_grid, 256, SMEM128>>>();
    k_gather128<<<gath_grid, 256>>>(b2);
    // layer 3
    k_splitW<<<(128 * 64 + 255) / 256, 256>>>(W3, 64);
    k_splitA<<<split_grid, 256>>>(nullptr, 1);
    k_gemm_mma<64><<<gemm_grid, 256, SMEM64>>>();
    k_gather64<<<gath_grid, 256>>>(b3);

    // pool + FC head
    k_pool<<<N_GRAPHS, 256>>>(batch);
    k_fc<<<1, 256>>>(Wf1, bf1, Wf2, bf2, (float*)d_out);
}

// round 7
// speedup vs baseline: 1.2630x; 1.0358x over previous
#include <cuda_runtime.h>
#include <cuda_bf16.h>
#include <cstdint>

#define N_NODES 50000
#define N_PAD   50048   // 391 * 128
#define N_EDGES 600000
#define N_GRAPHS 64
#define SCAN_CHUNK 1024
#define N_CHUNKS ((N_NODES + SCAN_CHUNK - 1) / SCAN_CHUNK)  // 49

// ---------------- scratch: referenced DIRECTLY in device code ----------------
__device__ int   g_is64;
__device__ float g_deg[N_NODES];                  // dinv
__device__ int   g_counts[N_NODES];
__device__ int   g_cursor[N_NODES];
__device__ int   g_rowptr[N_NODES + 1];
__device__ int   g_bsums[64];
__device__ int   g_esrc[N_EDGES];
__device__ float g_enorm[N_EDGES];
__device__ __align__(16) float g_bufA[(size_t)N_NODES * 128];  // GEMM out t
__device__ __align__(16) float g_bufB[(size_t)N_NODES * 128];  // layer-3 agg out
__device__ float g_pooled[N_GRAPHS * 64];
// bf16 split operands; padding rows [50000,50048) are never written -> stay zero
__device__ __align__(16) __nv_bfloat16 g_ahi[(size_t)N_PAD * 128];
__device__ __align__(16) __nv_bfloat16 g_alo[(size_t)N_PAD * 128];
// all three transposed weights: W1T @0, W2T @16384, W3T @32768 (elements)
__device__ __align__(16) __nv_bfloat16 g_whi[40960];
__device__ __align__(16) __nv_bfloat16 g_wlo[40960];

// ---------------- helpers ----------------
__device__ __forceinline__ uint32_t smem_u32(const void* p) {
    uint32_t a;
    asm("{ .reg .u64 t; cvta.to.shared.u64 t, %1; cvt.u32.u64 %0, t; }" : "=r"(a) : "l"(p));
    return a;
}
__device__ __forceinline__ void ldsm_x4(uint32_t* r, uint32_t addr) {
    asm volatile("ldmatrix.sync.aligned.m8n8.x4.shared.b16 {%0,%1,%2,%3}, [%4];"
                 : "=r"(r[0]), "=r"(r[1]), "=r"(r[2]), "=r"(r[3]) : "r"(addr));
}
__device__ __forceinline__ void mma_bf16(float* d, const uint32_t* a, uint32_t b0, uint32_t b1) {
    asm volatile(
        "mma.sync.aligned.m16n8k16.row.col.f32.bf16.bf16.f32 "
        "{%0,%1,%2,%3}, {%4,%5,%6,%7}, {%8,%9}, {%0,%1,%2,%3};"
        : "+f"(d[0]), "+f"(d[1]), "+f"(d[2]), "+f"(d[3])
        : "r"(a[0]), "r"(a[1]), "r"(a[2]), "r"(a[3]), "r"(b0), "r"(b1));
}
__device__ __forceinline__ int load_idx(const void* p, long long i) {
    if (g_is64) return (int)((const long long*)p)[i];
    return ((const int*)p)[i];
}
// pack two fp32 -> (hi bf16x2, lo bf16x2)
__device__ __forceinline__ void split2(float a, float b, uint32_t& hi, uint32_t& lo) {
    __nv_bfloat16 h0 = __float2bfloat16_rn(a), h1 = __float2bfloat16_rn(b);
    __nv_bfloat16 l0 = __float2bfloat16_rn(a - __bfloat162float(h0));
    __nv_bfloat16 l1 = __float2bfloat16_rn(b - __bfloat162float(h1));
    __nv_bfloat162 hp(h0, h1), lp(l0, l1);
    hi = *(uint32_t*)&hp;
    lo = *(uint32_t*)&lp;
}

// ---------------- init (+dtype detect) ----------------
__global__ void k_init(const int* __restrict__ ei32) {
    int i = blockIdx.x * blockDim.x + threadIdx.x;
    if (i == 0) {
        int hi = ei32[1] | ei32[3] | ei32[5] | ei32[7] | ei32[9] | ei32[11];
        g_is64 = (hi == 0) ? 1 : 0;
    }
    if (i < N_NODES) { g_counts[i] = 0; g_cursor[i] = 0; }
}

// ---------------- CSR build ----------------
__global__ void k_hist(const void* __restrict__ ei) {
    int i = blockIdx.x * blockDim.x + threadIdx.x;
    if (i < N_EDGES) {
        int c = load_idx(ei, (long long)N_EDGES + i);
        if ((unsigned)c < N_NODES) atomicAdd(&g_counts[c], 1);
    }
}
__global__ void k_scan1() {
    __shared__ int s[SCAN_CHUNK];
    int tid = threadIdx.x;
    int i = blockIdx.x * SCAN_CHUNK + tid;
    int v = (i < N_NODES) ? g_counts[i] : 0;
    s[tid] = v;
    __syncthreads();
#pragma unroll
    for (int off = 1; off < SCAN_CHUNK; off <<= 1) {
        int t = (tid >= off) ? s[tid - off] : 0;
        __syncthreads();
        s[tid] += t;
        __syncthreads();
    }
    if (i < N_NODES) g_rowptr[i] = s[tid] - v;
    if (tid == SCAN_CHUNK - 1) g_bsums[blockIdx.x] = s[tid];
}
__global__ void k_scan2() {
    if (threadIdx.x == 0 && blockIdx.x == 0) {
        int run = 0;
        for (int b = 0; b < N_CHUNKS; b++) { int v = g_bsums[b]; g_bsums[b] = run; run += v; }
        g_rowptr[N_NODES] = run;
    }
}
__global__ void k_scan3() {  // + rsqrt fused
    int i = blockIdx.x * blockDim.x + threadIdx.x;
    if (i < N_NODES) {
        g_rowptr[i] += g_bsums[i / SCAN_CHUNK];
        g_deg[i] = rsqrtf(1.0f + (float)g_counts[i]);  // + self loop
    }
}
__global__ void k_bucket(const void* __restrict__ ei) {
    int i = blockIdx.x * blockDim.x + threadIdx.x;
    if (i < N_EDGES) {
        int r = load_idx(ei, i);
        int c = load_idx(ei, (long long)N_EDGES + i);
        if ((unsigned)c < N_NODES && (unsigned)r < N_NODES) {
            int pos = g_rowptr[c] + atomicAdd(&g_cursor[c], 1);
            g_esrc[pos] = r;
            g_enorm[pos] = g_deg[r] * g_deg[c];
        }
    }
}

// ---------------- all W splits + transpose in one kernel ----------------
__global__ void k_splitW_all(const float* __restrict__ W1, const float* __restrict__ W2,
                             const float* __restrict__ W3) {
    int idx = blockIdx.x * blockDim.x + threadIdx.x;
    if (idx >= 40960) return;
    const float* W;
    int Ncols, local;
    if (idx < 16384)      { W = W1; Ncols = 128; local = idx; }
    else if (idx < 32768) { W = W2; Ncols = 128; local = idx - 16384; }
    else                  { W = W3; Ncols = 64;  local = idx - 32768; }
    int k = local & 127, n = local >> 7;
    float w = W[(size_t)k * Ncols + n];
    __nv_bfloat16 h = __float2bfloat16_rn(w);
    g_whi[idx] = h;
    g_wlo[idx] = __float2bfloat16_rn(w - __bfloat162float(h));
}

// ---------------- mma.sync GEMM: g_bufA[128-tile, NC] = (ahi+alo) @ WT ----
// 3-pass compensated bf16: hi*hi + hi*lo + lo*hi, fp32 accum.
// F32A: load fp32 A (x) and split to smem in-kernel (layer 1).
template <int NC, bool F32A>
__global__ void __launch_bounds__(256, 1) k_gemm_mma(const float* __restrict__ Aext, int wofs) {
    extern __shared__ __align__(16) char smem[];
    const int A_HI = 0, A_LO = 32768, B_HI = 65536, B_LO = 65536 + NC * 256;
    int tid = threadIdx.x;
    int wid = tid >> 5, lane = tid & 31;
    int row0 = blockIdx.x * 128;
    uint32_t sb = smem_u32(smem);

    if (F32A) {
        // load x fp32, split in-kernel. each thread: 16B chunks of hi/lo per 2 float4
        for (int c = tid; c < 128 * 32; c += 256) {   // c indexes float4 of a row
            int m = c >> 5, q = c & 31;               // q: float4 idx (0..31)
            float4 v = make_float4(0.f, 0.f, 0.f, 0.f);
            if (row0 + m < N_NODES)
                v = *reinterpret_cast<const float4*>(Aext + (size_t)(row0 + m) * 128 + q * 4);
            uint2 hv, lv;
            split2(v.x, v.y, hv.x, lv.x);
            split2(v.z, v.w, hv.y, lv.y);
            int kc = q >> 1;                          // 16B chunk
            int off = m * 256 + ((kc ^ (m & 7)) * 16) + (q & 1) * 8;
            *reinterpret_cast<uint2*>(smem + A_HI + off) = hv;
            *reinterpret_cast<uint2*>(smem + A_LO + off) = lv;
        }
    } else {
        for (int c = tid; c < 128 * 16; c += 256) {
            int m = c >> 4, kc = c & 15;
            size_t gof = ((size_t)(row0 + m)) * 256 + kc * 16;
            uint4 vh = *reinterpret_cast<const uint4*>(reinterpret_cast<const char*>(g_ahi) + gof);
            uint4 vl = *reinterpret_cast<const uint4*>(reinterpret_cast<const char*>(g_alo) + gof);
            int off = m * 256 + ((kc ^ (m & 7)) * 16);
            *reinterpret_cast<uint4*>(smem + A_HI + off) = vh;
            *reinterpret_cast<uint4*>(smem + A_LO + off) = vl;
        }
    }
    // B tiles (W^T slice, NC rows x 256B)
    const char* wh = reinterpret_cast<const char*>(g_whi + wofs);
    const char* wl = reinterpret_cast<const char*>(g_wlo + wofs);
    for (int c = tid; c < NC * 16; c += 256) {
        int n = c >> 4, kc = c & 15;
        size_t gof = (size_t)n * 256 + kc * 16;
        uint4 vh = *reinterpret_cast<const uint4*>(wh + gof);
        uint4 vl = *reinterpret_cast<const uint4*>(wl + gof);
        int off = n * 256 + ((kc ^ (n & 7)) * 16);
        *reinterpret_cast<uint4*>(smem + B_HI + off) = vh;
        *reinterpret_cast<uint4*>(smem + B_LO + off) = vl;
    }
    __syncthreads();

    const int NT = NC / 16;
    const int NP = NC / 32;
    int wm = (wid & 3) * 32;
    int wn = (wid >> 2) * (NC / 2);

    float acc[2][NT][4];
#pragma unroll
    for (int mt = 0; mt < 2; mt++)
#pragma unroll
        for (int nt = 0; nt < NT; nt++)
#pragma unroll
            for (int j = 0; j < 4; j++) acc[mt][nt][j] = 0.0f;

    for (int pass = 0; pass < 3; pass++) {
        int aB = (pass == 2) ? A_LO : A_HI;
        int bB = (pass == 1) ? B_LO : B_HI;
#pragma unroll
        for (int ks = 0; ks < 8; ks++) {
            uint32_t a[2][4];
#pragma unroll
            for (int mt = 0; mt < 2; mt++) {
                int r = wm + mt * 16 + (lane & 15);
                int ch = ks * 2 + (lane >> 4);
                ldsm_x4(a[mt], sb + aB + r * 256 + ((ch ^ (r & 7)) * 16));
            }
            uint32_t b[NP][4];
#pragma unroll
            for (int p = 0; p < NP; p++) {
                int n = wn + p * 16 + (lane & 7) + ((lane >> 4) << 3);
                int ch = ks * 2 + ((lane >> 3) & 1);
                ldsm_x4(b[p], sb + bB + n * 256 + ((ch ^ (n & 7)) * 16));
            }
#pragma unroll
            for (int mt = 0; mt < 2; mt++)
#pragma unroll
                for (int nt = 0; nt < NT; nt++)
                    mma_bf16(acc[mt][nt], a[mt], b[nt >> 1][(nt & 1) * 2], b[nt >> 1][(nt & 1) * 2 + 1]);
        }
    }

    int gid = lane >> 2, tig = lane & 3;
#pragma unroll
    for (int mt = 0; mt < 2; mt++) {
#pragma unroll
        for (int nt = 0; nt < NT; nt++) {
            int col = wn + nt * 8 + tig * 2;
            int m0 = row0 + wm + mt * 16 + gid;
            if (m0 < N_NODES)
                *reinterpret_cast<float2*>(g_bufA + (size_t)m0 * NC + col) =
                    make_float2(acc[mt][nt][0], acc[mt][nt][1]);
            if (m0 + 8 < N_NODES)
                *reinterpret_cast<float2*>(g_bufA + (size_t)(m0 + 8) * NC + col) =
                    make_float2(acc[mt][nt][2], acc[mt][nt][3]);
        }
    }
}

// ---------------- CSR gather + relu + bf16 split (layers 1,2) ----------------
__global__ void k_gather128_split(const float* __restrict__ b) {
    int node = (blockIdx.x * blockDim.x + threadIdx.x) >> 5;
    int lane = threadIdx.x & 31;
    if (node >= N_NODES) return;
    const float* t = g_bufA;
    float d = g_deg[node];
    float d2 = d * d;
    float4 self = *reinterpret_cast<const float4*>(t + (size_t)node * 128 + lane * 4);
    float4 bv = *reinterpret_cast<const float4*>(b + lane * 4);
    float4 acc;
    acc.x = fmaf(d2, self.x, bv.x);
    acc.y = fmaf(d2, self.y, bv.y);
    acc.z = fmaf(d2, self.z, bv.z);
    acc.w = fmaf(d2, self.w, bv.w);

    int s = g_rowptr[node], e = g_rowptr[node + 1];
    int i = s;
    for (; i + 1 < e; i += 2) {
        int r0 = g_esrc[i], r1 = g_esrc[i + 1];
        float w0 = g_enorm[i], w1 = g_enorm[i + 1];
        float4 v0 = *reinterpret_cast<const float4*>(t + (size_t)r0 * 128 + lane * 4);
        float4 v1 = *reinterpret_cast<const float4*>(t + (size_t)r1 * 128 + lane * 4);
        acc.x = fmaf(w0, v0.x, acc.x); acc.y = fmaf(w0, v0.y, acc.y);
        acc.z = fmaf(w0, v0.z, acc.z); acc.w = fmaf(w0, v0.w, acc.w);
        acc.x = fmaf(w1, v1.x, acc.x); acc.y = fmaf(w1, v1.y, acc.y);
        acc.z = fmaf(w1, v1.z, acc.z); acc.w = fmaf(w1, v1.w, acc.w);
    }
    if (i < e) {
        int r0 = g_esrc[i];
        float w0 = g_enorm[i];
        float4 v0 = *reinterpret_cast<const float4*>(t + (size_t)r0 * 128 + lane * 4);
        acc.x = fmaf(w0, v0.x, acc.x); acc.y = fmaf(w0, v0.y, acc.y);
        acc.z = fmaf(w0, v0.z, acc.z); acc.w = fmaf(w0, v0.w, acc.w);
    }
    // relu + hi/lo split, write next layer's A operand directly
    acc.x = fmaxf(acc.x, 0.0f); acc.y = fmaxf(acc.y, 0.0f);
    acc.z = fmaxf(acc.z, 0.0f); acc.w = fmaxf(acc.w, 0.0f);
    uint2 hv, lv;
    split2(acc.x, acc.y, hv.x, lv.x);
    split2(acc.z, acc.w, hv.y, lv.y);
    reinterpret_cast<uint2*>(g_ahi)[node * 32 + lane] = hv;
    reinterpret_cast<uint2*>(g_alo)[node * 32 + lane] = lv;
}

// layer-3 gather (F=64), fp32 out for pool
__global__ void k_gather64(const float* __restrict__ b) {
    int node = (blockIdx.x * blockDim.x + threadIdx.x) >> 5;
    int lane = threadIdx.x & 31;
    if (node >= N_NODES) return;
    const float* t = g_bufA;
    float d = g_deg[node];
    float d2 = d * d;
    float2 self = *reinterpret_cast<const float2*>(t + (size_t)node * 64 + lane * 2);
    float2 bv = *reinterpret_cast<const float2*>(b + lane * 2);
    float2 acc;
    acc.x = fmaf(d2, self.x, bv.x);
    acc.y = fmaf(d2, self.y, bv.y);

    int s = g_rowptr[node], e = g_rowptr[node + 1];
    int i = s;
    for (; i + 1 < e; i += 2) {
        int r0 = g_esrc[i], r1 = g_esrc[i + 1];
        float w0 = g_enorm[i], w1 = g_enorm[i + 1];
        float2 v0 = *reinterpret_cast<const float2*>(t + (size_t)r0 * 64 + lane * 2);
        float2 v1 = *reinterpret_cast<const float2*>(t + (size_t)r1 * 64 + lane * 2);
        acc.x = fmaf(w0, v0.x, acc.x); acc.y = fmaf(w0, v0.y, acc.y);
        acc.x = fmaf(w1, v1.x, acc.x); acc.y = fmaf(w1, v1.y, acc.y);
    }
    if (i < e) {
        int r0 = g_esrc[i];
        float w0 = g_enorm[i];
        float2 v0 = *reinterpret_cast<const float2*>(t + (size_t)r0 * 64 + lane * 2);
        acc.x = fmaf(w0, v0.x, acc.x); acc.y = fmaf(w0, v0.y, acc.y);
    }
    *reinterpret_cast<float2*>(g_bufB + (size_t)node * 64 + lane * 2) = acc;
}

// ---------------- mean pool (relu fused) ----------------
__global__ void k_pool(const void* __restrict__ batch) {
    int g = blockIdx.x;
    const int N = N_NODES;
    int lo = 0, hi = N;
    while (lo < hi) { int mid = (lo + hi) >> 1; if (load_idx(batch, mid) < g) lo = mid + 1; else hi = mid; }
    int start = lo;
    lo = start; hi = N;
    while (lo < hi) { int mid = (lo + hi) >> 1; if (load_idx(batch, mid) < g + 1) lo = mid + 1; else hi = mid; }
    int end = lo;

    int f = threadIdx.x & 63;
    int grp = threadIdx.x >> 6;
    __shared__ float red[4][64];

    float acc = 0.0f;
    for (int i = start + grp; i < end; i += 4)
        acc += fmaxf(g_bufB[(size_t)i * 64 + f], 0.0f);
    red[grp][f] = acc;
    __syncthreads();
    if (grp == 0) {
        float s = red[0][f] + red[1][f] + red[2][f] + red[3][f];
        float cnt = (float)(end - start);
        g_pooled[g * 64 + f] = s / fmaxf(cnt, 1.0f);
    }
}

// ---------------- FC head ----------------
__global__ void k_fc(const float* __restrict__ Wf1, const float* __restrict__ bf1,
                     const float* __restrict__ Wf2, const float* __restrict__ bf2,
                     float* __restrict__ out) {
    __shared__ float P[64 * 64];
    __shared__ float Hd[64 * 32];
    for (int i = threadIdx.x; i < 64 * 64; i += 256) P[i] = g_pooled[i];
    __syncthreads();
    for (int e = threadIdx.x; e < 64 * 32; e += 256) {
        int gi = e >> 5, j = e & 31;
        float s = bf1[j];
#pragma unroll
        for (int k = 0; k < 64; k++) s += P[gi * 64 + k] * Wf1[k * 32 + j];
        Hd[e] = fmaxf(s, 0.0f);
    }
    __syncthreads();
    for (int e = threadIdx.x; e < 64 * 10; e += 256) {
        int gi = e / 10, j = e % 10;
        float s = bf2[j];
#pragma unroll
        for (int k = 0; k < 32; k++) s += Hd[gi * 32 + k] * Wf2[k * 10 + j];
        out[e] = s;
    }
}

// ---------------- launch ----------------
extern "C" void kernel_launch(void* const* d_in, const int* in_sizes, int n_in,
                              void* d_out, int out_size) {
    const float *x = 0, *W1 = 0, *b1 = 0, *W2 = 0, *b2 = 0, *W3 = 0, *b3 = 0;
    const float *Wf1 = 0, *bf1 = 0, *Wf2 = 0, *bf2 = 0;
    const void *ei = 0, *batch = 0;
    for (int i = 0; i < n_in; i++) {
        const void* p = d_in[i];
        switch (in_sizes[i]) {
            case 6400000: x = (const float*)p; break;
            case 1200000: ei = p; break;
            case 50000:   batch = p; break;
            case 16384:   if (!W1) W1 = (const float*)p; else W2 = (const float*)p; break;
            case 128:     if (!b1) b1 = (const float*)p; else b2 = (const float*)p; break;
            case 8192:    W3 = (const float*)p; break;
            case 64:      b3 = (const float*)p; break;
            case 2048:    Wf1 = (const float*)p; break;
            case 32:      bf1 = (const float*)p; break;
            case 320:     Wf2 = (const float*)p; break;
            case 10:      bf2 = (const float*)p; break;
        }
    }

    const int N = N_NODES, E = N_EDGES;
    const int SMEM128 = 65536 + 2 * 128 * 256;  // 131072
    const int SMEM64  = 65536 + 2 * 64 * 256;   // 98304
    cudaFuncSetAttribute(k_gemm_mma<128, true>,  cudaFuncAttributeMaxDynamicSharedMemorySize, SMEM128);
    cudaFuncSetAttribute(k_gemm_mma<128, false>, cudaFuncAttributeMaxDynamicSharedMemorySize, SMEM128);
    cudaFuncSetAttribute(k_gemm_mma<64, false>,  cudaFuncAttributeMaxDynamicSharedMemorySize, SMEM64);

    // ---- CSR build ----
    k_init<<<(N + 255) / 256, 256>>>((const int*)ei);
    k_hist<<<(E + 255) / 256, 256>>>(ei);
    k_scan1<<<N_CHUNKS, SCAN_CHUNK>>>();
    k_scan2<<<1, 32>>>();
    k_scan3<<<(N + 255) / 256, 256>>>();
    k_bucket<<<(E + 255) / 256, 256>>>(ei);
    k_splitW_all<<<(40960 + 255) / 256, 256>>>(W1, W2, W3);

    int gath_grid = (N * 32 + 255) / 256;
    int gemm_grid = N_PAD / 128;  // 391

    // layer 1: GEMM splits x in-kernel; gather writes next A split directly
    k_gemm_mma<128, true><<<gemm_grid, 256, SMEM128>>>(x, 0);
    k_gather128_split<<<gath_grid, 256>>>(b1);
    // layer 2
    k_gemm_mma<128, false><<<gemm_grid, 256, SMEM128>>>(nullptr, 16384);
    k_gather128_split<<<gath_grid, 256>>>(b2);
    // layer 3
    k_gemm_mma<64, false><<<gemm_grid, 256, SMEM64>>>(nullptr, 32768);
    k_gather64<<<gath_grid, 256>>>(b3);

    // pool + FC head
    k_pool<<<N_GRAPHS, 256>>>(batch);
    k_fc<<<1, 256>>>(Wf1, bf1, Wf2, bf2, (float*)d_out);
}

// round 8
// speedup vs baseline: 1.3097x; 1.0369x over previous
#include <cuda_runtime.h>
#include <cuda_bf16.h>
#include <cstdint>

#define N_NODES 50000
#define N_PAD   50048   // 391 * 128
#define N_EDGES 600000
#define N_GRAPHS 64
#define SCAN_CHUNK 1024
#define N_CHUNKS ((N_NODES + SCAN_CHUNK - 1) / SCAN_CHUNK)  // 49

// ---------------- scratch: referenced DIRECTLY in device code ----------------
__device__ int   g_is64;
__device__ float g_deg[N_NODES];                  // dinv
__device__ int   g_counts[N_NODES];
__device__ int   g_cursor[N_NODES];
__device__ int   g_rowptr[N_NODES + 1];
__device__ int   g_bsums[64];
__device__ int   g_esrc[N_EDGES];
__device__ float g_enorm[N_EDGES];
__device__ __align__(16) float g_bufA[(size_t)N_NODES * 128];  // GEMM out t
__device__ __align__(16) float g_bufB[(size_t)N_NODES * 128];  // layer-3 agg out
__device__ float g_pooled[N_GRAPHS * 64];
// bf16 split operands; padding rows [50000,50048) are never written -> stay zero
__device__ __align__(16) __nv_bfloat16 g_ahi[(size_t)N_PAD * 128];
__device__ __align__(16) __nv_bfloat16 g_alo[(size_t)N_PAD * 128];
// all three transposed weights: W1T @0, W2T @16384, W3T @32768 (elements)
__device__ __align__(16) __nv_bfloat16 g_whi[40960];
__device__ __align__(16) __nv_bfloat16 g_wlo[40960];

// ---------------- helpers ----------------
__device__ __forceinline__ uint32_t smem_u32(const void* p) {
    uint32_t a;
    asm("{ .reg .u64 t; cvta.to.shared.u64 t, %1; cvt.u32.u64 %0, t; }" : "=r"(a) : "l"(p));
    return a;
}
__device__ __forceinline__ void ldsm_x4(uint32_t* r, uint32_t addr) {
    asm volatile("ldmatrix.sync.aligned.m8n8.x4.shared.b16 {%0,%1,%2,%3}, [%4];"
                 : "=r"(r[0]), "=r"(r[1]), "=r"(r[2]), "=r"(r[3]) : "r"(addr));
}
__device__ __forceinline__ void mma_bf16(float* d, const uint32_t* a, uint32_t b0, uint32_t b1) {
    asm volatile(
        "mma.sync.aligned.m16n8k16.row.col.f32.bf16.bf16.f32 "
        "{%0,%1,%2,%3}, {%4,%5,%6,%7}, {%8,%9}, {%0,%1,%2,%3};"
        : "+f"(d[0]), "+f"(d[1]), "+f"(d[2]), "+f"(d[3])
        : "r"(a[0]), "r"(a[1]), "r"(a[2]), "r"(a[3]), "r"(b0), "r"(b1));
}
__device__ __forceinline__ int load_idx(const void* p, long long i) {
    if (g_is64) return (int)((const long long*)p)[i];
    return ((const int*)p)[i];
}
__device__ __forceinline__ void split2(float a, float b, uint32_t& hi, uint32_t& lo) {
    __nv_bfloat16 h0 = __float2bfloat16_rn(a), h1 = __float2bfloat16_rn(b);
    __nv_bfloat16 l0 = __float2bfloat16_rn(a - __bfloat162float(h0));
    __nv_bfloat16 l1 = __float2bfloat16_rn(b - __bfloat162float(h1));
    __nv_bfloat162 hp(h0, h1), lp(l0, l1);
    hi = *(uint32_t*)&hp;
    lo = *(uint32_t*)&lp;
}

// ---------------- init: detect + counts/cursor reset + W splits ----------------
__global__ void k_init(const int* __restrict__ ei32, const float* __restrict__ W1,
                       const float* __restrict__ W2, const float* __restrict__ W3) {
    int i = blockIdx.x * blockDim.x + threadIdx.x;
    if (i == 0) {
        int hi = ei32[1] | ei32[3] | ei32[5] | ei32[7] | ei32[9] | ei32[11];
        g_is64 = (hi == 0) ? 1 : 0;
    }
    if (i < N_NODES) { g_counts[i] = 0; g_cursor[i] = 0; }
    if (i < 40960) {
        const float* W;
        int Ncols, local;
        if (i < 16384)      { W = W1; Ncols = 128; local = i; }
        else if (i < 32768) { W = W2; Ncols = 128; local = i - 16384; }
        else                { W = W3; Ncols = 64;  local = i - 32768; }
        int k = local & 127, n = local >> 7;
        float w = W[(size_t)k * Ncols + n];
        __nv_bfloat16 h = __float2bfloat16_rn(w);
        g_whi[i] = h;
        g_wlo[i] = __float2bfloat16_rn(w - __bfloat162float(h));
    }
}

// ---------------- CSR build ----------------
__global__ void k_hist(const void* __restrict__ ei) {
    int i = blockIdx.x * blockDim.x + threadIdx.x;
    if (i < N_EDGES) {
        int c = load_idx(ei, (long long)N_EDGES + i);
        if ((unsigned)c < N_NODES) atomicAdd(&g_counts[c], 1);
    }
}
__global__ void k_scan1() {
    __shared__ int s[SCAN_CHUNK];
    int tid = threadIdx.x;
    int i = blockIdx.x * SCAN_CHUNK + tid;
    int v = (i < N_NODES) ? g_counts[i] : 0;
    s[tid] = v;
    __syncthreads();
#pragma unroll
    for (int off = 1; off < SCAN_CHUNK; off <<= 1) {
        int t = (tid >= off) ? s[tid - off] : 0;
        __syncthreads();
        s[tid] += t;
        __syncthreads();
    }
    if (i < N_NODES) g_rowptr[i] = s[tid] - v;
    if (tid == SCAN_CHUNK - 1) g_bsums[blockIdx.x] = s[tid];
}
// fused: chunk-sum prefix (in-block warp scan) + rowptr fixup + rsqrt
__global__ void k_scan3() {
    __shared__ int pre[64];
    int tid = threadIdx.x;
    if (tid < 32) {
        unsigned full = 0xFFFFFFFFu;
        int v0 = (tid < N_CHUNKS) ? g_bsums[tid] : 0;
        int v1 = (tid + 32 < N_CHUNKS) ? g_bsums[tid + 32] : 0;
        int s0 = v0;
#pragma unroll
        for (int off = 1; off < 32; off <<= 1) {
            int t = __shfl_up_sync(full, s0, off);
            if (tid >= off) s0 += t;
        }
        int tot0 = __shfl_sync(full, s0, 31);
        int s1 = v1;
#pragma unroll
        for (int off = 1; off < 32; off <<= 1) {
            int t = __shfl_up_sync(full, s1, off);
            if (tid >= off) s1 += t;
        }
        s1 += tot0;
        pre[tid] = s0 - v0;            // exclusive prefix
        pre[tid + 32] = s1 - v1;
    }
    __syncthreads();
    int i = blockIdx.x * blockDim.x + tid;
    if (i < N_NODES) {
        g_rowptr[i] += pre[i / SCAN_CHUNK];
        g_deg[i] = rsqrtf(1.0f + (float)g_counts[i]);  // + self loop
    }
    if (i == 0) g_rowptr[N_NODES] = pre[N_CHUNKS - 1] + g_bsums[N_CHUNKS - 1];
}
__global__ void k_bucket(const void* __restrict__ ei) {
    int i = blockIdx.x * blockDim.x + threadIdx.x;
    if (i < N_EDGES) {
        int r = load_idx(ei, i);
        int c = load_idx(ei, (long long)N_EDGES + i);
        if ((unsigned)c < N_NODES && (unsigned)r < N_NODES) {
            int pos = g_rowptr[c] + atomicAdd(&g_cursor[c], 1);
            g_esrc[pos] = r;
            g_enorm[pos] = g_deg[r] * g_deg[c];
        }
    }
}

// ---------------- mma.sync GEMM: g_bufA[128-tile, NC] = (ahi+alo) @ WT ----
// compensated bf16: hi*hi + hi*lo + lo*hi in one K-loop (fragments loaded once).
template <int NC, bool F32A>
__global__ void __launch_bounds__(256, 1) k_gemm_mma(const float* __restrict__ Aext, int wofs) {
    extern __shared__ __align__(16) char smem[];
    const int A_HI = 0, A_LO = 32768, B_HI = 65536, B_LO = 65536 + NC * 256;
    int tid = threadIdx.x;
    int wid = tid >> 5, lane = tid & 31;
    int row0 = blockIdx.x * 128;
    uint32_t sb = smem_u32(smem);

    if (F32A) {
        for (int c = tid; c < 128 * 32; c += 256) {
            int m = c >> 5, q = c & 31;
            float4 v = make_float4(0.f, 0.f, 0.f, 0.f);
            if (row0 + m < N_NODES)
                v = *reinterpret_cast<const float4*>(Aext + (size_t)(row0 + m) * 128 + q * 4);
            uint2 hv, lv;
            split2(v.x, v.y, hv.x, lv.x);
            split2(v.z, v.w, hv.y, lv.y);
            int kc = q >> 1;
            int off = m * 256 + ((kc ^ (m & 7)) * 16) + (q & 1) * 8;
            *reinterpret_cast<uint2*>(smem + A_HI + off) = hv;
            *reinterpret_cast<uint2*>(smem + A_LO + off) = lv;
        }
    } else {
        for (int c = tid; c < 128 * 16; c += 256) {
            int m = c >> 4, kc = c & 15;
            size_t gof = ((size_t)(row0 + m)) * 256 + kc * 16;
            uint4 vh = *reinterpret_cast<const uint4*>(reinterpret_cast<const char*>(g_ahi) + gof);
            uint4 vl = *reinterpret_cast<const uint4*>(reinterpret_cast<const char*>(g_alo) + gof);
            int off = m * 256 + ((kc ^ (m & 7)) * 16);
            *reinterpret_cast<uint4*>(smem + A_HI + off) = vh;
            *reinterpret_cast<uint4*>(smem + A_LO + off) = vl;
        }
    }
    const char* wh = reinterpret_cast<const char*>(g_whi + wofs);
    const char* wl = reinterpret_cast<const char*>(g_wlo + wofs);
    for (int c = tid; c < NC * 16; c += 256) {
        int n = c >> 4, kc = c & 15;
        size_t gof = (size_t)n * 256 + kc * 16;
        uint4 vh = *reinterpret_cast<const uint4*>(wh + gof);
        uint4 vl = *reinterpret_cast<const uint4*>(wl + gof);
        int off = n * 256 + ((kc ^ (n & 7)) * 16);
        *reinterpret_cast<uint4*>(smem + B_HI + off) = vh;
        *reinterpret_cast<uint4*>(smem + B_LO + off) = vl;
    }
    __syncthreads();

    const int NT = NC / 16;
    const int NP = NC / 32;
    int wm = (wid & 3) * 32;
    int wn = (wid >> 2) * (NC / 2);

    float acc[2][NT][4];
#pragma unroll
    for (int mt = 0; mt < 2; mt++)
#pragma unroll
        for (int nt = 0; nt < NT; nt++)
#pragma unroll
            for (int j = 0; j < 4; j++) acc[mt][nt][j] = 0.0f;

#pragma unroll
    for (int ks = 0; ks < 8; ks++) {
        uint32_t ah[2][4], al[2][4];
#pragma unroll
        for (int mt = 0; mt < 2; mt++) {
            int r = wm + mt * 16 + (lane & 15);
            int ch = ks * 2 + (lane >> 4);
            int off = r * 256 + ((ch ^ (r & 7)) * 16);
            ldsm_x4(ah[mt], sb + A_HI + off);
            ldsm_x4(al[mt], sb + A_LO + off);
        }
        uint32_t bh[NP][4], bl[NP][4];
#pragma unroll
        for (int p = 0; p < NP; p++) {
            int n = wn + p * 16 + (lane & 7) + ((lane >> 4) << 3);
            int ch = ks * 2 + ((lane >> 3) & 1);
            int off = n * 256 + ((ch ^ (n & 7)) * 16);
            ldsm_x4(bh[p], sb + B_HI + off);
            ldsm_x4(bl[p], sb + B_LO + off);
        }
#pragma unroll
        for (int mt = 0; mt < 2; mt++)
#pragma unroll
            for (int nt = 0; nt < NT; nt++) {
                uint32_t h0 = bh[nt >> 1][(nt & 1) * 2], h1 = bh[nt >> 1][(nt & 1) * 2 + 1];
                uint32_t l0 = bl[nt >> 1][(nt & 1) * 2], l1 = bl[nt >> 1][(nt & 1) * 2 + 1];
                mma_bf16(acc[mt][nt], ah[mt], h0, h1);
                mma_bf16(acc[mt][nt], ah[mt], l0, l1);
                mma_bf16(acc[mt][nt], al[mt], h0, h1);
            }
    }

    int gid = lane >> 2, tig = lane & 3;
#pragma unroll
    for (int mt = 0; mt < 2; mt++) {
#pragma unroll
        for (int nt = 0; nt < NT; nt++) {
            int col = wn + nt * 8 + tig * 2;
            int m0 = row0 + wm + mt * 16 + gid;
            if (m0 < N_NODES)
                *reinterpret_cast<float2*>(g_bufA + (size_t)m0 * NC + col) =
                    make_float2(acc[mt][nt][0], acc[mt][nt][1]);
            if (m0 + 8 < N_NODES)
                *reinterpret_cast<float2*>(g_bufA + (size_t)(m0 + 8) * NC + col) =
                    make_float2(acc[mt][nt][2], acc[mt][nt][3]);
        }
    }
}

// ---------------- CSR gather + relu + bf16 split (layers 1,2) ----------------
__global__ void k_gather128_split(const float* __restrict__ b) {
    int node = (blockIdx.x * blockDim.x + threadIdx.x) >> 5;
    int lane = threadIdx.x & 31;
    if (node >= N_NODES) return;
    const float* t = g_bufA;
    float d = g_deg[node];
    float d2 = d * d;
    float4 self = *reinterpret_cast<const float4*>(t + (size_t)node * 128 + lane * 4);
    float4 bv = *reinterpret_cast<const float4*>(b + lane * 4);
    float4 acc;
    acc.x = fmaf(d2, self.x, bv.x);
    acc.y = fmaf(d2, self.y, bv.y);
    acc.z = fmaf(d2, self.z, bv.z);
    acc.w = fmaf(d2, self.w, bv.w);

    int s = g_rowptr[node], e = g_rowptr[node + 1];
    int i = s;
    for (; i + 1 < e; i += 2) {
        int r0 = g_esrc[i], r1 = g_esrc[i + 1];
        float w0 = g_enorm[i], w1 = g_enorm[i + 1];
        float4 v0 = *reinterpret_cast<const float4*>(t + (size_t)r0 * 128 + lane * 4);
        float4 v1 = *reinterpret_cast<const float4*>(t + (size_t)r1 * 128 + lane * 4);
        acc.x = fmaf(w0, v0.x, acc.x); acc.y = fmaf(w0, v0.y, acc.y);
        acc.z = fmaf(w0, v0.z, acc.z); acc.w = fmaf(w0, v0.w, acc.w);
        acc.x = fmaf(w1, v1.x, acc.x); acc.y = fmaf(w1, v1.y, acc.y);
        acc.z = fmaf(w1, v1.z, acc.z); acc.w = fmaf(w1, v1.w, acc.w);
    }
    if (i < e) {
        int r0 = g_esrc[i];
        float w0 = g_enorm[i];
        float4 v0 = *reinterpret_cast<const float4*>(t + (size_t)r0 * 128 + lane * 4);
        acc.x = fmaf(w0, v0.x, acc.x); acc.y = fmaf(w0, v0.y, acc.y);
        acc.z = fmaf(w0, v0.z, acc.z); acc.w = fmaf(w0, v0.w, acc.w);
    }
    acc.x = fmaxf(acc.x, 0.0f); acc.y = fmaxf(acc.y, 0.0f);
    acc.z = fmaxf(acc.z, 0.0f); acc.w = fmaxf(acc.w, 0.0f);
    uint2 hv, lv;
    split2(acc.x, acc.y, hv.x, lv.x);
    split2(acc.z, acc.w, hv.y, lv.y);
    reinterpret_cast<uint2*>(g_ahi)[node * 32 + lane] = hv;
    reinterpret_cast<uint2*>(g_alo)[node * 32 + lane] = lv;
}

// layer-3 gather (F=64), fp32 out for pool
__global__ void k_gather64(const float* __restrict__ b) {
    int node = (blockIdx.x * blockDim.x + threadIdx.x) >> 5;
    int lane = threadIdx.x & 31;
    if (node >= N_NODES) return;
    const float* t = g_bufA;
    float d = g_deg[node];
    float d2 = d * d;
    float2 self = *reinterpret_cast<const float2*>(t + (size_t)node * 64 + lane * 2);
    float2 bv = *reinterpret_cast<const float2*>(b + lane * 2);
    float2 acc;
    acc.x = fmaf(d2, self.x, bv.x);
    acc.y = fmaf(d2, self.y, bv.y);

    int s = g_rowptr[node], e = g_rowptr[node + 1];
    int i = s;
    for (; i + 1 < e; i += 2) {
        int r0 = g_esrc[i], r1 = g_esrc[i + 1];
        float w0 = g_enorm[i], w1 = g_enorm[i + 1];
        float2 v0 = *reinterpret_cast<const float2*>(t + (size_t)r0 * 64 + lane * 2);
        float2 v1 = *reinterpret_cast<const float2*>(t + (size_t)r1 * 64 + lane * 2);
        acc.x = fmaf(w0, v0.x, acc.x); acc.y = fmaf(w0, v0.y, acc.y);
        acc.x = fmaf(w1, v1.x, acc.x); acc.y = fmaf(w1, v1.y, acc.y);
    }
    if (i < e) {
        int r0 = g_esrc[i];
        float w0 = g_enorm[i];
        float2 v0 = *reinterpret_cast<const float2*>(t + (size_t)r0 * 64 + lane * 2);
        acc.x = fmaf(w0, v0.x, acc.x); acc.y = fmaf(w0, v0.y, acc.y);
    }
    *reinterpret_cast<float2*>(g_bufB + (size_t)node * 64 + lane * 2) = acc;
}

// ---------------- mean pool (relu fused) ----------------
__global__ void k_pool(const void* __restrict__ batch) {
    int g = blockIdx.x;
    const int N = N_NODES;
    int lo = 0, hi = N;
    while (lo < hi) { int mid = (lo + hi) >> 1; if (load_idx(batch, mid) < g) lo = mid + 1; else hi = mid; }
    int start = lo;
    lo = start; hi = N;
    while (lo < hi) { int mid = (lo + hi) >> 1; if (load_idx(batch, mid) < g + 1) lo = mid + 1; else hi = mid; }
    int end = lo;

    int f = threadIdx.x & 63;
    int grp = threadIdx.x >> 6;
    __shared__ float red[4][64];

    float acc = 0.0f;
    for (int i = start + grp; i < end; i += 4)
        acc += fmaxf(g_bufB[(size_t)i * 64 + f], 0.0f);
    red[grp][f] = acc;
    __syncthreads();
    if (grp == 0) {
        float s = red[0][f] + red[1][f] + red[2][f] + red[3][f];
        float cnt = (float)(end - start);
        g_pooled[g * 64 + f] = s / fmaxf(cnt, 1.0f);
    }
}

// ---------------- FC head ----------------
__global__ void k_fc(const float* __restrict__ Wf1, const float* __restrict__ bf1,
                     const float* __restrict__ Wf2, const float* __restrict__ bf2,
                     float* __restrict__ out) {
    __shared__ float P[64 * 64];
    __shared__ float Hd[64 * 32];
    for (int i = threadIdx.x; i < 64 * 64; i += 256) P[i] = g_pooled[i];
    __syncthreads();
    for (int e = threadIdx.x; e < 64 * 32; e += 256) {
        int gi = e >> 5, j = e & 31;
        float s = bf1[j];
#pragma unroll
        for (int k = 0; k < 64; k++) s += P[gi * 64 + k] * Wf1[k * 32 + j];
        Hd[e] = fmaxf(s, 0.0f);
    }
    __syncthreads();
    for (int e = threadIdx.x; e < 64 * 10; e += 256) {
        int gi = e / 10, j = e % 10;
        float s = bf2[j];
#pragma unroll
        for (int k = 0; k < 32; k++) s += Hd[gi * 32 + k] * Wf2[k * 10 + j];
        out[e] = s;
    }
}

// ---------------- launch ----------------
extern "C" void kernel_launch(void* const* d_in, const int* in_sizes, int n_in,
                              void* d_out, int out_size) {
    const float *x = 0, *W1 = 0, *b1 = 0, *W2 = 0, *b2 = 0, *W3 = 0, *b3 = 0;
    const float *Wf1 = 0, *bf1 = 0, *Wf2 = 0, *bf2 = 0;
    const void *ei = 0, *batch = 0;
    for (int i = 0; i < n_in; i++) {
        const void* p = d_in[i];
        switch (in_sizes[i]) {
            case 6400000: x = (const float*)p; break;
            case 1200000: ei = p; break;
            case 50000:   batch = p; break;
            case 16384:   if (!W1) W1 = (const float*)p; else W2 = (const float*)p; break;
            case 128:     if (!b1) b1 = (const float*)p; else b2 = (const float*)p; break;
            case 8192:    W3 = (const float*)p; break;
            case 64:      b3 = (const float*)p; break;
            case 2048:    Wf1 = (const float*)p; break;
            case 32:      bf1 = (const float*)p; break;
            case 320:     Wf2 = (const float*)p; break;
            case 10:      bf2 = (const float*)p; break;
        }
    }

    const int N = N_NODES, E = N_EDGES;
    const int SMEM128 = 65536 + 2 * 128 * 256;  // 131072
    const int SMEM64  = 65536 + 2 * 64 * 256;   // 98304
    cudaFuncSetAttribute(k_gemm_mma<128, true>,  cudaFuncAttributeMaxDynamicSharedMemorySize, SMEM128);
    cudaFuncSetAttribute(k_gemm_mma<128, false>, cudaFuncAttributeMaxDynamicSharedMemorySize, SMEM128);
    cudaFuncSetAttribute(k_gemm_mma<64, false>,  cudaFuncAttributeMaxDynamicSharedMemorySize, SMEM64);

    // ---- CSR build ----
    k_init<<<(N + 255) / 256, 256>>>((const int*)ei, W1, W2, W3);
    k_hist<<<(E + 255) / 256, 256>>>(ei);
    k_scan1<<<N_CHUNKS, SCAN_CHUNK>>>();
    k_scan3<<<(N + 255) / 256, 256>>>();
    k_bucket<<<(E + 255) / 256, 256>>>(ei);

    int gath_grid = (N * 32 + 255) / 256;
    int gemm_grid = N_PAD / 128;  // 391

    // layer 1
    k_gemm_mma<128, true><<<gemm_grid, 256, SMEM128>>>(x, 0);
    k_gather128_split<<<gath_grid, 256>>>(b1);
    // layer 2
    k_gemm_mma<128, false><<<gemm_grid, 256, SMEM128>>>(nullptr, 16384);
    k_gather128_split<<<gath_grid, 256>>>(b2);
    // layer 3
    k_gemm_mma<64, false><<<gemm_grid, 256, SMEM64>>>(nullptr, 32768);
    k_gather64<<<gath_grid, 256>>>(b3);

    // pool + FC head
    k_pool<<<N_GRAPHS, 256>>>(batch);
    k_fc<<<1, 256>>>(Wf1, bf1, Wf2, bf2, (float*)d_out);
}